// round 2
// baseline (speedup 1.0000x reference)
#include <cuda_runtime.h>
#include <cuda_fp16.h>
#include <cstdint>

// Problem constants
#define NSEQ  16384      // B*Ns = 32*512
#define TLEN  128
#define CDIM  25
#define PDIM  20
#define HDIM  25
#define NPAIR 40         // padded gate slots: 3 gates x 26 units + 2 pad = 80 -> 40 pairs
// pair p: gate g = p/13 (g==3 -> pad pair 39), q = p%13, units u0=2q, u1=2q+1 (u<25 valid)

typedef unsigned long long ull;

// ---------------- packed f32x2 helpers (sm_100+ only, ptxas never auto-emits) -------------
__device__ __forceinline__ ull ffma2(ull a, ull b, ull c) {
    ull d;
    asm("fma.rn.f32x2 %0, %1, %2, %3;" : "=l"(d) : "l"(a), "l"(b), "l"(c));
    return d;
}
__device__ __forceinline__ ull fdup(float v) {
    ull r;
    asm("mov.b64 %0, {%1, %1};" : "=l"(r) : "f"(v));
    return r;
}
__device__ __forceinline__ void f2unpack(ull v, float& lo, float& hi) {
    asm("mov.b64 {%0, %1}, %2;" : "=f"(lo), "=f"(hi) : "l"(v));
}
__device__ __forceinline__ float ex2f(float x) {
    float r; asm("ex2.approx.f32 %0, %1;" : "=f"(r) : "f"(x)); return r;
}
__device__ __forceinline__ float rcpf(float x) {
    float r; asm("rcp.approx.f32 %0, %1;" : "=f"(r) : "f"(x)); return r;
}
// sigmoid(x) = 1/(1+2^(-x*log2e));  tanh(x) = 2/(1+2^(-2x*log2e)) - 1   (~1e-6 accurate)
__device__ __forceinline__ float sigf(float x) {
    return rcpf(1.0f + ex2f(-1.4426950408889634f * x));
}
__device__ __forceinline__ float tanhfast(float x) {
    float e = ex2f(-2.8853900817779268f * x);
    return fmaf(2.0f, rcpf(1.0f + e), -1.0f);
}
__device__ __forceinline__ ull pkbits(float lo, float hi) {
    return (ull)__float_as_uint(lo) | ((ull)__float_as_uint(hi) << 32);
}

// ---------------- device scratch (static: no allocation) ----------------
__device__ ull g_pW1[CDIM * 10];        // [k][jp] pairs of W1 columns
__device__ ull g_pb1[10];
__device__ ull g_pWih[PDIM * NPAIR];    // [k][pair] padded-slot layout
__device__ ull g_bias_gx[NPAIR];        // b_ih (+ b_hh for r,z gates) in padded slots
__device__ ull g_pWhh[HDIM * NPAIR];    // [k][pair] padded-slot layout
__device__ ull g_acc_init[NPAIR];       // b_hh for n gate only (stays recurrent-side)
__device__ __half2 g_gx[(size_t)TLEN * NSEQ * NPAIR];  // 335 MB scratch, [t][n][pair]

// ---------------- prep: pack weights ----------------
__global__ void prep_kernel(const float* __restrict__ W1, const float* __restrict__ b1,
                            const float* __restrict__ Wih, const float* __restrict__ Whh,
                            const float* __restrict__ bih, const float* __restrict__ bhh) {
    int tid = threadIdx.x;
    for (int i = tid; i < CDIM * 10; i += blockDim.x) {
        int k = i / 10, jp = i % 10;
        g_pW1[i] = pkbits(W1[(2 * jp) * CDIM + k], W1[(2 * jp + 1) * CDIM + k]);
    }
    for (int i = tid; i < 10; i += blockDim.x)
        g_pb1[i] = pkbits(b1[2 * i], b1[2 * i + 1]);

    for (int i = tid; i < PDIM * NPAIR; i += blockDim.x) {
        int k = i / NPAIR, p = i % NPAIR;
        int g = p / 13, q = p % 13;
        float lo = 0.f, hi = 0.f;
        if (g < 3) {
            int u0 = 2 * q, u1 = u0 + 1;
            if (u0 < 25) lo = Wih[(g * 25 + u0) * PDIM + k];
            if (u1 < 25) hi = Wih[(g * 25 + u1) * PDIM + k];
        }
        g_pWih[i] = pkbits(lo, hi);
    }
    for (int i = tid; i < HDIM * NPAIR; i += blockDim.x) {
        int k = i / NPAIR, p = i % NPAIR;
        int g = p / 13, q = p % 13;
        float lo = 0.f, hi = 0.f;
        if (g < 3) {
            int u0 = 2 * q, u1 = u0 + 1;
            if (u0 < 25) lo = Whh[(g * 25 + u0) * HDIM + k];
            if (u1 < 25) hi = Whh[(g * 25 + u1) * HDIM + k];
        }
        g_pWhh[i] = pkbits(lo, hi);
    }
    for (int i = tid; i < NPAIR; i += blockDim.x) {
        int p = i, g = p / 13, q = p % 13;
        float lo = 0.f, hi = 0.f;
        if (g < 3) {
            int u0 = 2 * q, u1 = u0 + 1;
            if (u0 < 25) lo = bih[g * 25 + u0] + (g < 2 ? bhh[g * 25 + u0] : 0.f);
            if (u1 < 25) hi = bih[g * 25 + u1] + (g < 2 ? bhh[g * 25 + u1] : 0.f);
        }
        g_bias_gx[i] = pkbits(lo, hi);
    }
    for (int i = tid; i < NPAIR; i += blockDim.x) {
        int p = i, g = p / 13, q = p % 13;
        float lo = 0.f, hi = 0.f;
        if (g == 2) {
            int u0 = 2 * q, u1 = u0 + 1;
            if (u0 < 25) lo = bhh[50 + u0];
            if (u1 < 25) hi = bhh[50 + u1];
        }
        g_acc_init[i] = pkbits(lo, hi);
    }
}

// ---------------- K1: gx = leakyrelu(x@W1^T + b1) @ Wih^T + biases  -> fp16 -----------
// 2 rows (t, t+1) per thread; lanes = consecutive n for coalesced stores.
__global__ __launch_bounds__(128, 1) void gx_kernel(const float* __restrict__ x) {
    __shared__ ull sW1[CDIM * 10];
    __shared__ ull sb1[10];
    __shared__ ull sWih[PDIM * NPAIR];
    __shared__ ull sbias[NPAIR];
    for (int i = threadIdx.x; i < CDIM * 10; i += 128) sW1[i] = g_pW1[i];
    for (int i = threadIdx.x; i < 10; i += 128) sb1[i] = g_pb1[i];
    for (int i = threadIdx.x; i < PDIM * NPAIR; i += 128) sWih[i] = g_pWih[i];
    for (int i = threadIdx.x; i < NPAIR; i += 128) sbias[i] = g_bias_gx[i];
    __syncthreads();

    int n = blockIdx.x * 128 + threadIdx.x;
    int t0 = blockIdx.y * 2;

    // load x rows t0, t0+1 : 50 contiguous floats (8B-aligned since t0 even)
    const float2* xp = reinterpret_cast<const float2*>(x + ((size_t)n * TLEN + t0) * CDIM);
    float xv[50];
#pragma unroll
    for (int i = 0; i < 25; i++) {
        float2 v = __ldg(xp + i);
        xv[2 * i] = v.x; xv[2 * i + 1] = v.y;
    }

    // projection: p = x@W1^T + b1 (packed across output pairs, weight reuse across rows)
    ull pa0[10], pa1[10];
#pragma unroll
    for (int j = 0; j < 10; j++) { pa0[j] = sb1[j]; pa1[j] = sb1[j]; }
#pragma unroll
    for (int k = 0; k < CDIM; k++) {
        ull d0 = fdup(xv[k]);
        ull d1 = fdup(xv[25 + k]);
        const ulonglong2* row = reinterpret_cast<const ulonglong2*>(&sW1[k * 10]);
#pragma unroll
        for (int j = 0; j < 5; j++) {
            ulonglong2 w = row[j];
            pa0[2 * j]     = ffma2(w.x, d0, pa0[2 * j]);
            pa0[2 * j + 1] = ffma2(w.y, d0, pa0[2 * j + 1]);
            pa1[2 * j]     = ffma2(w.x, d1, pa1[2 * j]);
            pa1[2 * j + 1] = ffma2(w.y, d1, pa1[2 * j + 1]);
        }
    }
    // LeakyReLU(v) = max(v, 0.01v)
    float pv0[20], pv1[20];
#pragma unroll
    for (int j = 0; j < 10; j++) {
        float a, b;
        f2unpack(pa0[j], a, b);
        pv0[2 * j] = fmaxf(a, 0.01f * a); pv0[2 * j + 1] = fmaxf(b, 0.01f * b);
        f2unpack(pa1[j], a, b);
        pv1[2 * j] = fmaxf(a, 0.01f * a); pv1[2 * j + 1] = fmaxf(b, 0.01f * b);
    }

    uint4* dst0 = reinterpret_cast<uint4*>(g_gx + ((size_t)t0 * NSEQ + n) * NPAIR);
    uint4* dst1 = reinterpret_cast<uint4*>(g_gx + ((size_t)(t0 + 1) * NSEQ + n) * NPAIR);

    // gx stage in 2 chunks of 20 pairs to bound register pressure
#pragma unroll
    for (int c = 0; c < 2; c++) {
        ull ga0[20], ga1[20];
#pragma unroll
        for (int q = 0; q < 20; q++) { ga0[q] = sbias[c * 20 + q]; ga1[q] = sbias[c * 20 + q]; }
#pragma unroll
        for (int k = 0; k < PDIM; k++) {
            ull d0 = fdup(pv0[k]);
            ull d1 = fdup(pv1[k]);
            const ulonglong2* row =
                reinterpret_cast<const ulonglong2*>(&sWih[k * NPAIR + c * 20]);
#pragma unroll
            for (int q = 0; q < 10; q++) {
                ulonglong2 w = row[q];
                ga0[2 * q]     = ffma2(w.x, d0, ga0[2 * q]);
                ga0[2 * q + 1] = ffma2(w.y, d0, ga0[2 * q + 1]);
                ga1[2 * q]     = ffma2(w.x, d1, ga1[2 * q]);
                ga1[2 * q + 1] = ffma2(w.y, d1, ga1[2 * q + 1]);
            }
        }
        union { __half2 h2[20]; uint4 v4[5]; } ob0, ob1;
#pragma unroll
        for (int q = 0; q < 20; q++) {
            float a, b;
            f2unpack(ga0[q], a, b);
            ob0.h2[q] = __floats2half2_rn(a, b);
            f2unpack(ga1[q], a, b);
            ob1.h2[q] = __floats2half2_rn(a, b);
        }
#pragma unroll
        for (int i = 0; i < 5; i++) {
            dst0[c * 5 + i] = ob0.v4[i];
            dst1[c * 5 + i] = ob1.v4[i];
        }
    }
}

// ---------------- K2: GRU scan, thread-per-sequence ----------------
// Restructured step to overlap the n-gate dot product with the r/z MUFU phase:
//   1) rz-acc (pairs 0..25, zero-init: biases already folded into gx)
//   2) r/z sigmoids            } mutually independent -> ptxas interleaves,
//   3) n-acc  (pairs 26..38)   } hiding the MUFU-pipe time under FFMA2 issue
//   4) n = tanh(gn + r*accn), h update
__global__ __launch_bounds__(128, 1) void gru_kernel(float* __restrict__ out) {
    __shared__ ull sW[HDIM * NPAIR];   // 8 KB, broadcast reads, layout [k][pair]
    __shared__ ull sInitN[13];         // b_hh(n) pairs (slots 26..38)
    for (int i = threadIdx.x; i < HDIM * NPAIR; i += 128) sW[i] = g_pWhh[i];
    for (int i = threadIdx.x; i < 13; i += 128) sInitN[i] = g_acc_init[26 + i];
    __syncthreads();

    int n = blockIdx.x * 128 + threadIdx.x;
    float h[26];
#pragma unroll
    for (int u = 0; u < 26; u++) h[u] = 0.f;

#pragma unroll 1
    for (int t = 0; t < TLEN; t++) {
        // issue gx loads first; consumed ~1300 cycles later (after rz-acc) -> DRAM hidden
        union { uint4 v4[10]; __half2 h2[40]; } gx;
        const uint4* gp = reinterpret_cast<const uint4*>(g_gx + ((size_t)t * NSEQ + n) * NPAIR);
#pragma unroll
        for (int i = 0; i < 10; i++) gx.v4[i] = __ldg(gp + i);

        // ---- phase 1: rz accumulators (pairs 0..25), zero-init ----
        ull acc[26];
#pragma unroll
        for (int p = 0; p < 26; p++) acc[p] = 0ull;
#pragma unroll
        for (int k = 0; k < HDIM; k++) {
            ull hd = fdup(h[k]);
            const ulonglong2* row = reinterpret_cast<const ulonglong2*>(&sW[k * NPAIR]);
#pragma unroll
            for (int p = 0; p < 13; p++) {
                ulonglong2 w = row[p];
                acc[2 * p]     = ffma2(w.x, hd, acc[2 * p]);
                acc[2 * p + 1] = ffma2(w.y, hd, acc[2 * p + 1]);
            }
        }

        // ---- phase 2: r/z sigmoids (MUFU-heavy, independent of phase 3) ----
        float rv[26], zv[26];
#pragma unroll
        for (int p = 0; p < 13; p++) {
            float2 gr = __half22float2(gx.h2[p]);
            float2 gz = __half22float2(gx.h2[13 + p]);
            float arl, arh; f2unpack(acc[p], arl, arh);
            float azl, azh; f2unpack(acc[13 + p], azl, azh);
            rv[2 * p]     = sigf(gr.x + arl);
            rv[2 * p + 1] = sigf(gr.y + arh);
            zv[2 * p]     = sigf(gz.x + azl);
            zv[2 * p + 1] = sigf(gz.y + azh);
        }

        // ---- phase 3: n accumulators (pairs 26..38), FFMA2 work overlapping phase 2 ----
        ull accn[13];
#pragma unroll
        for (int p = 0; p < 13; p++) accn[p] = sInitN[p];
#pragma unroll
        for (int k = 0; k < HDIM; k++) {
            ull hd = fdup(h[k]);
            const ulonglong2* rowN =
                reinterpret_cast<const ulonglong2*>(&sW[k * NPAIR + 26]);
#pragma unroll
            for (int p = 0; p < 6; p++) {
                ulonglong2 w = rowN[p];
                accn[2 * p]     = ffma2(w.x, hd, accn[2 * p]);
                accn[2 * p + 1] = ffma2(w.y, hd, accn[2 * p + 1]);
            }
            accn[12] = ffma2(sW[k * NPAIR + 38], hd, accn[12]);
        }

        // ---- phase 4: n gate + h update ----
#pragma unroll
        for (int p = 0; p < 13; p++) {
            float2 gn = __half22float2(gx.h2[26 + p]);
            float anl, anh; f2unpack(accn[p], anl, anh);
            float nl = tanhfast(fmaf(rv[2 * p],     anl, gn.x));
            float nh = tanhfast(fmaf(rv[2 * p + 1], anh, gn.y));
            h[2 * p]     = fmaf(zv[2 * p],     h[2 * p]     - nl, nl);
            h[2 * p + 1] = fmaf(zv[2 * p + 1], h[2 * p + 1] - nh, nh);
        }
    }
#pragma unroll
    for (int u = 0; u < HDIM; u++) out[(size_t)n * HDIM + u] = h[u];
}

// ---------------- launcher ----------------
extern "C" void kernel_launch(void* const* d_in, const int* in_sizes, int n_in,
                              void* d_out, int out_size) {
    (void)in_sizes; (void)n_in; (void)out_size;
    const float* x   = (const float*)d_in[0];
    const float* W1  = (const float*)d_in[1];
    const float* b1  = (const float*)d_in[2];
    const float* Wih = (const float*)d_in[3];
    const float* Whh = (const float*)d_in[4];
    const float* bih = (const float*)d_in[5];
    const float* bhh = (const float*)d_in[6];

    prep_kernel<<<1, 256>>>(W1, b1, Wih, Whh, bih, bhh);
    gx_kernel<<<dim3(NSEQ / 128, TLEN / 2), 128>>>(x);
    gru_kernel<<<NSEQ / 128, 128>>>((float*)d_out);
}

// round 7
// speedup vs baseline: 1.3476x; 1.3476x over previous
#include <cuda_runtime.h>
#include <cuda_fp16.h>
#include <cstdint>

// Problem constants
#define NSEQ  16384      // B*Ns = 32*512
#define TLEN  128
#define CDIM  25
#define PDIM  20
#define HDIM  25
#define NPAIR 40         // padded gate slots: 3 gates x 26 units + 2 pad = 80 -> 40 pairs
// pair p: gate g = p/13 (g==3 -> pad pair 39), q = p%13, units u0=2q, u1=2q+1 (u<25 valid)

typedef unsigned long long ull;

// ---------------- packed f32x2 / misc helpers -------------
__device__ __forceinline__ ull ffma2(ull a, ull b, ull c) {
    ull d;
    asm("fma.rn.f32x2 %0, %1, %2, %3;" : "=l"(d) : "l"(a), "l"(b), "l"(c));
    return d;
}
__device__ __forceinline__ ull fdup(float v) {
    ull r;
    asm("mov.b64 %0, {%1, %1};" : "=l"(r) : "f"(v));
    return r;
}
__device__ __forceinline__ void f2unpack(ull v, float& lo, float& hi) {
    asm("mov.b64 {%0, %1}, %2;" : "=f"(lo), "=f"(hi) : "l"(v));
}
__device__ __forceinline__ float tanhx(float x) {
    float r; asm("tanh.approx.f32 %0, %1;" : "=f"(r) : "f"(x)); return r;
}
__device__ __forceinline__ ull pkbits(float lo, float hi) {
    return (ull)__float_as_uint(lo) | ((ull)__float_as_uint(hi) << 32);
}
__device__ __forceinline__ void cpa16(uint32_t smem_addr, const void* gptr) {
    asm volatile("cp.async.cg.shared.global [%0], [%1], 16;"
                 :: "r"(smem_addr), "l"(gptr));
}
__device__ __forceinline__ void cpa_commit() {
    asm volatile("cp.async.commit_group;");
}
__device__ __forceinline__ void cpa_wait1() {
    asm volatile("cp.async.wait_group 1;");
}

// ---------------- device scratch (static: no allocation) ----------------
__device__ ull g_pW1[CDIM * 10];        // [k][jp] pairs of W1 columns
__device__ ull g_pb1[10];
__device__ ull g_pWih[PDIM * NPAIR];    // [k][pair]; r,z rows pre-scaled by 0.5
__device__ ull g_bias_gx[NPAIR];        // r,z: 0.5*(b_ih+b_hh); n: b_ih
__device__ ull g_pWhh[HDIM * NPAIR];    // [k][pair]; r,z rows pre-scaled by 0.5
__device__ ull g_acc_init[13];          // b_hh for n gate pairs only
__device__ __half2 g_gx[(size_t)TLEN * NSEQ * NPAIR];  // 335 MB scratch, [t][n][pair]

// ---------------- prep: pack weights ----------------
// sigmoid is computed as 0.5 + 0.5*tanh(arg/2); the /2 is folded here into the
// r,z rows of W_ih, W_hh and their biases.
__global__ void prep_kernel(const float* __restrict__ W1, const float* __restrict__ b1,
                            const float* __restrict__ Wih, const float* __restrict__ Whh,
                            const float* __restrict__ bih, const float* __restrict__ bhh) {
    int tid = threadIdx.x;
    for (int i = tid; i < CDIM * 10; i += blockDim.x) {
        int k = i / 10, jp = i % 10;
        g_pW1[i] = pkbits(W1[(2 * jp) * CDIM + k], W1[(2 * jp + 1) * CDIM + k]);
    }
    for (int i = tid; i < 10; i += blockDim.x)
        g_pb1[i] = pkbits(b1[2 * i], b1[2 * i + 1]);

    for (int i = tid; i < PDIM * NPAIR; i += blockDim.x) {
        int k = i / NPAIR, p = i % NPAIR;
        int g = p / 13, q = p % 13;
        float lo = 0.f, hi = 0.f;
        if (g < 3) {
            float s = (g < 2) ? 0.5f : 1.0f;
            int u0 = 2 * q, u1 = u0 + 1;
            if (u0 < 25) lo = s * Wih[(g * 25 + u0) * PDIM + k];
            if (u1 < 25) hi = s * Wih[(g * 25 + u1) * PDIM + k];
        }
        g_pWih[i] = pkbits(lo, hi);
    }
    for (int i = tid; i < HDIM * NPAIR; i += blockDim.x) {
        int k = i / NPAIR, p = i % NPAIR;
        int g = p / 13, q = p % 13;
        float lo = 0.f, hi = 0.f;
        if (g < 3) {
            float s = (g < 2) ? 0.5f : 1.0f;
            int u0 = 2 * q, u1 = u0 + 1;
            if (u0 < 25) lo = s * Whh[(g * 25 + u0) * HDIM + k];
            if (u1 < 25) hi = s * Whh[(g * 25 + u1) * HDIM + k];
        }
        g_pWhh[i] = pkbits(lo, hi);
    }
    for (int i = tid; i < NPAIR; i += blockDim.x) {
        int p = i, g = p / 13, q = p % 13;
        float lo = 0.f, hi = 0.f;
        if (g < 3) {
            int u0 = 2 * q, u1 = u0 + 1;
            if (g < 2) {  // r,z: fold recurrent bias AND the sigmoid half-scale
                if (u0 < 25) lo = 0.5f * (bih[g * 25 + u0] + bhh[g * 25 + u0]);
                if (u1 < 25) hi = 0.5f * (bih[g * 25 + u1] + bhh[g * 25 + u1]);
            } else {      // n: only input-side bias here
                if (u0 < 25) lo = bih[50 + u0];
                if (u1 < 25) hi = bih[50 + u1];
            }
        }
        g_bias_gx[i] = pkbits(lo, hi);
    }
    for (int i = tid; i < 13; i += blockDim.x) {
        int q = i;
        float lo = 0.f, hi = 0.f;
        int u0 = 2 * q, u1 = u0 + 1;
        if (u0 < 25) lo = bhh[50 + u0];
        if (u1 < 25) hi = bhh[50 + u1];
        g_acc_init[i] = pkbits(lo, hi);
    }
}

// ---------------- K1: gx = leakyrelu(x@W1^T + b1) @ Wih^T + biases  -> fp16 -----------
// 2 rows (t, t+1) per thread; lanes = consecutive n for coalesced stores.
__global__ __launch_bounds__(128, 1) void gx_kernel(const float* __restrict__ x) {
    __shared__ ull sW1[CDIM * 10];
    __shared__ ull sb1[10];
    __shared__ ull sWih[PDIM * NPAIR];
    __shared__ ull sbias[NPAIR];
    for (int i = threadIdx.x; i < CDIM * 10; i += 128) sW1[i] = g_pW1[i];
    for (int i = threadIdx.x; i < 10; i += 128) sb1[i] = g_pb1[i];
    for (int i = threadIdx.x; i < PDIM * NPAIR; i += 128) sWih[i] = g_pWih[i];
    for (int i = threadIdx.x; i < NPAIR; i += 128) sbias[i] = g_bias_gx[i];
    __syncthreads();

    int n = blockIdx.x * 128 + threadIdx.x;
    int t0 = blockIdx.y * 2;

    const float2* xp = reinterpret_cast<const float2*>(x + ((size_t)n * TLEN + t0) * CDIM);
    float xv[50];
#pragma unroll
    for (int i = 0; i < 25; i++) {
        float2 v = __ldg(xp + i);
        xv[2 * i] = v.x; xv[2 * i + 1] = v.y;
    }

    ull pa0[10], pa1[10];
#pragma unroll
    for (int j = 0; j < 10; j++) { pa0[j] = sb1[j]; pa1[j] = sb1[j]; }
#pragma unroll
    for (int k = 0; k < CDIM; k++) {
        ull d0 = fdup(xv[k]);
        ull d1 = fdup(xv[25 + k]);
        const ulonglong2* row = reinterpret_cast<const ulonglong2*>(&sW1[k * 10]);
#pragma unroll
        for (int j = 0; j < 5; j++) {
            ulonglong2 w = row[j];
            pa0[2 * j]     = ffma2(w.x, d0, pa0[2 * j]);
            pa0[2 * j + 1] = ffma2(w.y, d0, pa0[2 * j + 1]);
            pa1[2 * j]     = ffma2(w.x, d1, pa1[2 * j]);
            pa1[2 * j + 1] = ffma2(w.y, d1, pa1[2 * j + 1]);
        }
    }
    float pv0[20], pv1[20];
#pragma unroll
    for (int j = 0; j < 10; j++) {
        float a, b;
        f2unpack(pa0[j], a, b);
        pv0[2 * j] = fmaxf(a, 0.01f * a); pv0[2 * j + 1] = fmaxf(b, 0.01f * b);
        f2unpack(pa1[j], a, b);
        pv1[2 * j] = fmaxf(a, 0.01f * a); pv1[2 * j + 1] = fmaxf(b, 0.01f * b);
    }

    uint4* dst0 = reinterpret_cast<uint4*>(g_gx + ((size_t)t0 * NSEQ + n) * NPAIR);
    uint4* dst1 = reinterpret_cast<uint4*>(g_gx + ((size_t)(t0 + 1) * NSEQ + n) * NPAIR);

#pragma unroll
    for (int c = 0; c < 2; c++) {
        ull ga0[20], ga1[20];
#pragma unroll
        for (int q = 0; q < 20; q++) { ga0[q] = sbias[c * 20 + q]; ga1[q] = sbias[c * 20 + q]; }
#pragma unroll
        for (int k = 0; k < PDIM; k++) {
            ull d0 = fdup(pv0[k]);
            ull d1 = fdup(pv1[k]);
            const ulonglong2* row =
                reinterpret_cast<const ulonglong2*>(&sWih[k * NPAIR + c * 20]);
#pragma unroll
            for (int q = 0; q < 10; q++) {
                ulonglong2 w = row[q];
                ga0[2 * q]     = ffma2(w.x, d0, ga0[2 * q]);
                ga0[2 * q + 1] = ffma2(w.y, d0, ga0[2 * q + 1]);
                ga1[2 * q]     = ffma2(w.x, d1, ga1[2 * q]);
                ga1[2 * q + 1] = ffma2(w.y, d1, ga1[2 * q + 1]);
            }
        }
        union { __half2 h2[20]; uint4 v4[5]; } ob0, ob1;
#pragma unroll
        for (int q = 0; q < 20; q++) {
            float a, b;
            f2unpack(ga0[q], a, b);
            ob0.h2[q] = __floats2half2_rn(a, b);
            f2unpack(ga1[q], a, b);
            ob1.h2[q] = __floats2half2_rn(a, b);
        }
#pragma unroll
        for (int i = 0; i < 5; i++) {
            dst0[c * 5 + i] = ob0.v4[i];
            dst1[c * 5 + i] = ob1.v4[i];
        }
    }
}

// ---------------- K2: GRU scan, thread-per-sequence ----------------
// cp.async double-buffered gx prefetch (DRAM latency off the critical path),
// tanh.approx gates (78 MUFU/step instead of 156, shorter dep chains).
#define GXSTRIDE 176   // bytes per thread slot (padded from 160 -> conflict-free LDS.128)

__global__ __launch_bounds__(128, 1) void gru_kernel(float* __restrict__ out) {
    __shared__ ull sW[HDIM * NPAIR];                 // 8 KB, [k][pair], broadcast reads
    __shared__ ull sInitN[13];
    __shared__ __align__(16) char sGx[2][128 * GXSTRIDE];   // 44 KB ping-pong
    for (int i = threadIdx.x; i < HDIM * NPAIR; i += 128) sW[i] = g_pWhh[i];
    for (int i = threadIdx.x; i < 13; i += 128) sInitN[i] = g_acc_init[i];
    __syncthreads();

    int n = blockIdx.x * 128 + threadIdx.x;
    const char* gbase = reinterpret_cast<const char*>(g_gx) + (size_t)n * (NPAIR * 4);

    uint32_t slot0, slot1;
    {
        uint32_t b;
        asm("{ .reg .u64 t; cvta.to.shared.u64 t, %1; cvt.u32.u64 %0, t; }"
            : "=r"(b) : "l"((void*)&sGx[0][threadIdx.x * GXSTRIDE]));
        slot0 = b;
        slot1 = b + 128 * GXSTRIDE;
    }

    // prefetch t=0 into buffer 0
    {
        const char* g = gbase;  // t=0
#pragma unroll
        for (int i = 0; i < 10; i++) cpa16(slot0 + i * 16, g + i * 16);
        cpa_commit();
    }

    float h[26];
#pragma unroll
    for (int u = 0; u < 26; u++) h[u] = 0.f;

#pragma unroll 1
    for (int t = 0; t < TLEN; t++) {
        uint32_t cur = (t & 1) ? slot1 : slot0;
        uint32_t nxt = (t & 1) ? slot0 : slot1;
        // prefetch gx[t+1]
        if (t + 1 < TLEN) {
            const char* g = gbase + (size_t)(t + 1) * (NSEQ * NPAIR * 4);
#pragma unroll
            for (int i = 0; i < 10; i++) cpa16(nxt + i * 16, g + i * 16);
        }
        cpa_commit();

        // ---- recurrent accumulators: r,z pairs 0..25 (zero-init) + n pairs (bias) ----
        ull accA[26];
        ull accN[13];
#pragma unroll
        for (int p = 0; p < 26; p++) accA[p] = 0ull;
#pragma unroll
        for (int p = 0; p < 13; p++) accN[p] = sInitN[p];
#pragma unroll
        for (int k = 0; k < HDIM; k++) {
            ull hd = fdup(h[k]);
            const ulonglong2* row = reinterpret_cast<const ulonglong2*>(&sW[k * NPAIR]);
#pragma unroll
            for (int p = 0; p < 13; p++) {
                ulonglong2 w = row[p];
                accA[2 * p]     = ffma2(w.x, hd, accA[2 * p]);
                accA[2 * p + 1] = ffma2(w.y, hd, accA[2 * p + 1]);
            }
#pragma unroll
            for (int p = 0; p < 6; p++) {
                ulonglong2 w = row[13 + p];
                accN[2 * p]     = ffma2(w.x, hd, accN[2 * p]);
                accN[2 * p + 1] = ffma2(w.y, hd, accN[2 * p + 1]);
            }
            accN[12] = ffma2(sW[k * NPAIR + 38], hd, accN[12]);
        }

        // ---- gx[t] guaranteed resident (wait_group 1 keeps only the newest in flight) --
        cpa_wait1();
        union { uint4 v4[10]; __half2 h2[40]; } gx;
#pragma unroll
        for (int i = 0; i < 10; i++) {
            asm volatile("ld.shared.v4.u32 {%0,%1,%2,%3}, [%4];"
                         : "=r"(gx.v4[i].x), "=r"(gx.v4[i].y),
                           "=r"(gx.v4[i].z), "=r"(gx.v4[i].w)
                         : "r"(cur + i * 16));
        }

        // ---- gates: sig(v) = 0.5 + 0.5*tanh(v/2), the /2 pre-folded into weights ----
#pragma unroll
        for (int p = 0; p < 13; p++) {
            float2 gr = __half22float2(gx.h2[p]);
            float2 gz = __half22float2(gx.h2[13 + p]);
            float2 gn = __half22float2(gx.h2[26 + p]);
            float arl, arh; f2unpack(accA[p], arl, arh);
            float azl, azh; f2unpack(accA[13 + p], azl, azh);
            float anl, anh; f2unpack(accN[p], anl, anh);
            float rl = fmaf(0.5f, tanhx(gr.x + arl), 0.5f);
            float rh = fmaf(0.5f, tanhx(gr.y + arh), 0.5f);
            float zl = fmaf(0.5f, tanhx(gz.x + azl), 0.5f);
            float zh = fmaf(0.5f, tanhx(gz.y + azh), 0.5f);
            float nl = tanhx(fmaf(rl, anl, gn.x));
            float nh = tanhx(fmaf(rh, anh, gn.y));
            h[2 * p]     = fmaf(zl, h[2 * p] - nl, nl);
            h[2 * p + 1] = fmaf(zh, h[2 * p + 1] - nh, nh);
        }
    }
#pragma unroll
    for (int u = 0; u < HDIM; u++) out[(size_t)n * HDIM + u] = h[u];
}

// ---------------- launcher ----------------
extern "C" void kernel_launch(void* const* d_in, const int* in_sizes, int n_in,
                              void* d_out, int out_size) {
    (void)in_sizes; (void)n_in; (void)out_size;
    const float* x   = (const float*)d_in[0];
    const float* W1  = (const float*)d_in[1];
    const float* b1  = (const float*)d_in[2];
    const float* Wih = (const float*)d_in[3];
    const float* Whh = (const float*)d_in[4];
    const float* bih = (const float*)d_in[5];
    const float* bhh = (const float*)d_in[6];

    prep_kernel<<<1, 256>>>(W1, b1, Wih, Whh, bih, bhh);
    gx_kernel<<<dim3(NSEQ / 128, TLEN / 2), 128>>>(x);
    gru_kernel<<<NSEQ / 128, 128>>>((float*)d_out);
}

// round 9
// speedup vs baseline: 1.4216x; 1.0549x over previous
#include <cuda_runtime.h>
#include <cuda_fp16.h>
#include <cstdint>

// Problem constants
#define NSEQ   16384     // B*Ns
#define TLEN   128
#define CDIM   25
#define PDIM   20
#define HDIM   25
#define SLOTS  44        // padded gate-pair slots:
//  lo half (units 0..13):  slots 0..6 = r pairs, 7..13 = z, 14..20 = n, 21..23 pad
//  hi half (units 14..25): slots 24..29 = r, 30..35 = z, 36..41 = n, 42..43 pad
#define NCHUNK 11        // 44 half2 = 11 x 16B chunks; lo owns chunks 0..5, hi 6..10

typedef unsigned long long ull;

// ---------------- packed f32x2 / misc helpers -------------
__device__ __forceinline__ ull ffma2(ull a, ull b, ull c) {
    ull d;
    asm("fma.rn.f32x2 %0, %1, %2, %3;" : "=l"(d) : "l"(a), "l"(b), "l"(c));
    return d;
}
__device__ __forceinline__ ull fdup(float v) {
    ull r;
    asm("mov.b64 %0, {%1, %1};" : "=l"(r) : "f"(v));
    return r;
}
__device__ __forceinline__ void f2unpack(ull v, float& lo, float& hi) {
    asm("mov.b64 {%0, %1}, %2;" : "=f"(lo), "=f"(hi) : "l"(v));
}
__device__ __forceinline__ float tanhx(float x) {
    float r; asm("tanh.approx.f32 %0, %1;" : "=f"(r) : "f"(x)); return r;
}
__device__ __forceinline__ ull pkbits(float lo, float hi) {
    return (ull)__float_as_uint(lo) | ((ull)__float_as_uint(hi) << 32);
}
__device__ __forceinline__ void cpa16(uint32_t smem_addr, const void* gptr) {
    asm volatile("cp.async.cg.shared.global [%0], [%1], 16;"
                 :: "r"(smem_addr), "l"(gptr));
}
__device__ __forceinline__ void cpa_commit() {
    asm volatile("cp.async.commit_group;");
}
__device__ __forceinline__ void cpa_wait1() {
    asm volatile("cp.async.wait_group 1;");
}
__device__ __forceinline__ uint32_t s2u(const void* p) {
    uint32_t a;
    asm("{ .reg .u64 t; cvta.to.shared.u64 t, %1; cvt.u32.u64 %0, t; }"
        : "=r"(a) : "l"(p));
    return a;
}

// slot -> (gate, first unit).  returns gate<0 for pad slots.
__device__ __forceinline__ void slot_decode(int s, int& g, int& u0) {
    if (s < 21)                { g = s / 7;        u0 = 2 * (s % 7); }
    else if (s >= 24 && s < 42){ int s2 = s - 24;  g = s2 / 6;  u0 = 14 + 2 * (s2 % 6); }
    else                       { g = -1; u0 = 0; }
}

// ---------------- device scratch (static: no allocation) ----------------
__device__ ull g_pW1[CDIM * 10];          // [k][jp] pairs of W1 columns
__device__ ull g_pb1[10];
__device__ ull g_pWih[PDIM * SLOTS];      // [k][slot]; r,z pre-scaled by 0.5
__device__ ull g_bias_gx[SLOTS];          // r,z: 0.5*(b_ih+b_hh); n: b_ih; pads 0
__device__ ull g_pWhh[HDIM * SLOTS];      // [k][slot]; r,z pre-scaled by 0.5
__device__ ull g_acc_init[SLOTS];         // b_hh on n slots, else 0
__device__ uint4 g_gx[(size_t)TLEN * NCHUNK * NSEQ];   // 369 MB, [t][chunk][n]

// ---------------- prep: pack weights into the split-slot layout ----------------
__global__ void prep_kernel(const float* __restrict__ W1, const float* __restrict__ b1,
                            const float* __restrict__ Wih, const float* __restrict__ Whh,
                            const float* __restrict__ bih, const float* __restrict__ bhh) {
    int tid = threadIdx.x;
    for (int i = tid; i < CDIM * 10; i += blockDim.x) {
        int k = i / 10, jp = i % 10;
        g_pW1[i] = pkbits(W1[(2 * jp) * CDIM + k], W1[(2 * jp + 1) * CDIM + k]);
    }
    for (int i = tid; i < 10; i += blockDim.x)
        g_pb1[i] = pkbits(b1[2 * i], b1[2 * i + 1]);

    for (int i = tid; i < PDIM * SLOTS; i += blockDim.x) {
        int k = i / SLOTS, s = i % SLOTS;
        int g, u0; slot_decode(s, g, u0);
        float lo = 0.f, hi = 0.f;
        if (g >= 0) {
            float sc = (g < 2) ? 0.5f : 1.0f;
            if (u0 < 25)     lo = sc * Wih[(g * 25 + u0) * PDIM + k];
            if (u0 + 1 < 25) hi = sc * Wih[(g * 25 + u0 + 1) * PDIM + k];
        }
        g_pWih[i] = pkbits(lo, hi);
    }
    for (int i = tid; i < HDIM * SLOTS; i += blockDim.x) {
        int k = i / SLOTS, s = i % SLOTS;
        int g, u0; slot_decode(s, g, u0);
        float lo = 0.f, hi = 0.f;
        if (g >= 0) {
            float sc = (g < 2) ? 0.5f : 1.0f;
            if (u0 < 25)     lo = sc * Whh[(g * 25 + u0) * HDIM + k];
            if (u0 + 1 < 25) hi = sc * Whh[(g * 25 + u0 + 1) * HDIM + k];
        }
        g_pWhh[i] = pkbits(lo, hi);
    }
    for (int i = tid; i < SLOTS; i += blockDim.x) {
        int g, u0; slot_decode(i, g, u0);
        float lo = 0.f, hi = 0.f;
        if (g >= 0 && g < 2) {   // r,z: fold both biases + sigmoid half-scale
            if (u0 < 25)     lo = 0.5f * (bih[g * 25 + u0] + bhh[g * 25 + u0]);
            if (u0 + 1 < 25) hi = 0.5f * (bih[g * 25 + u0 + 1] + bhh[g * 25 + u0 + 1]);
        } else if (g == 2) {     // n: input-side bias only
            if (u0 < 25)     lo = bih[50 + u0];
            if (u0 + 1 < 25) hi = bih[50 + u0 + 1];
        }
        g_bias_gx[i] = pkbits(lo, hi);
    }
    for (int i = tid; i < SLOTS; i += blockDim.x) {
        int g, u0; slot_decode(i, g, u0);
        float lo = 0.f, hi = 0.f;
        if (g == 2) {            // n: recurrent bias stays on acc side
            if (u0 < 25)     lo = bhh[50 + u0];
            if (u0 + 1 < 25) hi = bhh[50 + u0 + 1];
        }
        g_acc_init[i] = pkbits(lo, hi);
    }
}

// ---------------- K1: gx -> fp16, chunk-major [t][chunk][n] ----------------
__global__ __launch_bounds__(128, 1) void gx_kernel(const float* __restrict__ x) {
    __shared__ ull sW1[CDIM * 10];
    __shared__ ull sb1[10];
    __shared__ ull sWih[PDIM * SLOTS];
    __shared__ ull sbias[SLOTS];
    for (int i = threadIdx.x; i < CDIM * 10; i += 128) sW1[i] = g_pW1[i];
    for (int i = threadIdx.x; i < 10; i += 128) sb1[i] = g_pb1[i];
    for (int i = threadIdx.x; i < PDIM * SLOTS; i += 128) sWih[i] = g_pWih[i];
    for (int i = threadIdx.x; i < SLOTS; i += 128) sbias[i] = g_bias_gx[i];
    __syncthreads();

    int n = blockIdx.x * 128 + threadIdx.x;
    int t0 = blockIdx.y * 2;

    const float2* xp = reinterpret_cast<const float2*>(x + ((size_t)n * TLEN + t0) * CDIM);
    float xv[50];
#pragma unroll
    for (int i = 0; i < 25; i++) {
        float2 v = __ldg(xp + i);
        xv[2 * i] = v.x; xv[2 * i + 1] = v.y;
    }

    // projection
    ull pa0[10], pa1[10];
#pragma unroll
    for (int j = 0; j < 10; j++) { pa0[j] = sb1[j]; pa1[j] = sb1[j]; }
#pragma unroll
    for (int k = 0; k < CDIM; k++) {
        ull d0 = fdup(xv[k]);
        ull d1 = fdup(xv[25 + k]);
        const ulonglong2* row = reinterpret_cast<const ulonglong2*>(&sW1[k * 10]);
#pragma unroll
        for (int j = 0; j < 5; j++) {
            ulonglong2 w = row[j];
            pa0[2 * j]     = ffma2(w.x, d0, pa0[2 * j]);
            pa0[2 * j + 1] = ffma2(w.y, d0, pa0[2 * j + 1]);
            pa1[2 * j]     = ffma2(w.x, d1, pa1[2 * j]);
            pa1[2 * j + 1] = ffma2(w.y, d1, pa1[2 * j + 1]);
        }
    }
    float pv0[20], pv1[20];
#pragma unroll
    for (int j = 0; j < 10; j++) {
        float a, b;
        f2unpack(pa0[j], a, b);
        pv0[2 * j] = fmaxf(a, 0.01f * a); pv0[2 * j + 1] = fmaxf(b, 0.01f * b);
        f2unpack(pa1[j], a, b);
        pv1[2 * j] = fmaxf(a, 0.01f * a); pv1[2 * j + 1] = fmaxf(b, 0.01f * b);
    }

    // ---- chunk A: slots 0..23 (lo half) ----
    {
        ull ga0[24], ga1[24];
#pragma unroll
        for (int q = 0; q < 24; q++) { ga0[q] = sbias[q]; ga1[q] = sbias[q]; }
#pragma unroll
        for (int k = 0; k < PDIM; k++) {
            ull d0 = fdup(pv0[k]);
            ull d1 = fdup(pv1[k]);
            const ulonglong2* row = reinterpret_cast<const ulonglong2*>(&sWih[k * SLOTS]);
#pragma unroll
            for (int q = 0; q < 12; q++) {
                ulonglong2 w = row[q];
                ga0[2 * q]     = ffma2(w.x, d0, ga0[2 * q]);
                ga0[2 * q + 1] = ffma2(w.y, d0, ga0[2 * q + 1]);
                ga1[2 * q]     = ffma2(w.x, d1, ga1[2 * q]);
                ga1[2 * q + 1] = ffma2(w.y, d1, ga1[2 * q + 1]);
            }
        }
        union { __half2 h2[24]; uint4 v4[6]; } ob0, ob1;
#pragma unroll
        for (int q = 0; q < 24; q++) {
            float a, b;
            f2unpack(ga0[q], a, b); ob0.h2[q] = __floats2half2_rn(a, b);
            f2unpack(ga1[q], a, b); ob1.h2[q] = __floats2half2_rn(a, b);
        }
#pragma unroll
        for (int ci = 0; ci < 6; ci++) {
            g_gx[((size_t)t0 * NCHUNK + ci) * NSEQ + n]       = ob0.v4[ci];
            g_gx[((size_t)(t0 + 1) * NCHUNK + ci) * NSEQ + n] = ob1.v4[ci];
        }
    }
    // ---- chunk B: slots 24..43 (hi half) ----
    {
        ull ga0[20], ga1[20];
#pragma unroll
        for (int q = 0; q < 20; q++) { ga0[q] = sbias[24 + q]; ga1[q] = sbias[24 + q]; }
#pragma unroll
        for (int k = 0; k < PDIM; k++) {
            ull d0 = fdup(pv0[k]);
            ull d1 = fdup(pv1[k]);
            const ulonglong2* row =
                reinterpret_cast<const ulonglong2*>(&sWih[k * SLOTS + 24]);
#pragma unroll
            for (int q = 0; q < 10; q++) {
                ulonglong2 w = row[q];
                ga0[2 * q]     = ffma2(w.x, d0, ga0[2 * q]);
                ga0[2 * q + 1] = ffma2(w.y, d0, ga0[2 * q + 1]);
                ga1[2 * q]     = ffma2(w.x, d1, ga1[2 * q]);
                ga1[2 * q + 1] = ffma2(w.y, d1, ga1[2 * q + 1]);
            }
        }
        union { __half2 h2[20]; uint4 v4[5]; } ob0, ob1;
#pragma unroll
        for (int q = 0; q < 20; q++) {
            float a, b;
            f2unpack(ga0[q], a, b); ob0.h2[q] = __floats2half2_rn(a, b);
            f2unpack(ga1[q], a, b); ob1.h2[q] = __floats2half2_rn(a, b);
        }
#pragma unroll
        for (int ci = 0; ci < 5; ci++) {
            g_gx[((size_t)t0 * NCHUNK + 6 + ci) * NSEQ + n]       = ob0.v4[ci];
            g_gx[((size_t)(t0 + 1) * NCHUNK + 6 + ci) * NSEQ + n] = ob1.v4[ci];
        }
    }
}

// ---------------- K2: GRU scan, TWO threads per sequence ----------------
// CTA = 256 threads = 128 seqs x {lo: units 0..13, hi: units 14..25}.
// lo = warps 0..3, hi = warps 4..7 -> every SMSP runs one lo + one hi warp,
// so each warp's stalls are hidden by the other's issue.
#define SMEM_GX  (2 * NCHUNK * 128 * 16)   // 45056 B ping-pong gx
#define SMEM_SH  (2 * 25 * 128 * 4)        // 25600 B ping-pong h exchange
#define SMEM_SW  (HDIM * SLOTS * 8)        // 8800 B weights
#define SMEM_TOT (SMEM_GX + SMEM_SH + SMEM_SW + SLOTS * 8)

__global__ __launch_bounds__(256, 1) void gru_kernel(float* __restrict__ out) {
    extern __shared__ __align__(16) char dyn[];
    uint4* sGx   = reinterpret_cast<uint4*>(dyn);                       // [2][NCHUNK*128]
    float* sH    = reinterpret_cast<float*>(dyn + SMEM_GX);             // [2][25*128]
    ull*   sW    = reinterpret_cast<ull*>(dyn + SMEM_GX + SMEM_SH);     // [25*SLOTS]
    ull*   sInit = sW + HDIM * SLOTS;                                   // [SLOTS]

    int tid = threadIdx.x;
    for (int i = tid; i < HDIM * SLOTS; i += 256) sW[i] = g_pWhh[i];
    for (int i = tid; i < SLOTS; i += 256) sInit[i] = g_acc_init[i];
    for (int i = tid; i < 25 * 128; i += 256) sH[i] = 0.f;   // sH buffer 0 = h(0) = 0
    __syncthreads();

    const bool lo = tid < 128;
    const int sidx = lo ? tid : tid - 128;
    const int n = blockIdx.x * 128 + sidx;
    const int cbase = lo ? 0 : 6;
    const int cnum  = lo ? 6 : 5;

    uint32_t gxs0 = s2u(sGx);
    uint32_t gxs1 = gxs0 + NCHUNK * 128 * 16;
    const char* gxg = reinterpret_cast<const char*>(g_gx);

    // n-gate recurrent bias pairs, cached in registers (hi reads slot 42 = pad 0)
    ull bIn[7];
#pragma unroll
    for (int j = 0; j < 7; j++) bIn[j] = sInit[(lo ? 14 : 36) + j];

    // prefetch t=0 into buffer 0
    {
        const char* g = gxg + (((size_t)0 * NCHUNK + cbase) * NSEQ + n) * 16;
        uint32_t d = gxs0 + (cbase * 128 + sidx) * 16;
        for (int j = 0; j < cnum; j++) cpa16(d + j * 2048, g + (size_t)j * NSEQ * 16);
        cpa_commit();
    }

    float hfull[25];
#pragma unroll
    for (int u = 0; u < 25; u++) hfull[u] = 0.f;

#pragma unroll 1
    for (int t = 0; t < TLEN; t++) {
        const int rb = t & 1, wb = rb ^ 1;
        uint32_t cur = rb ? gxs1 : gxs0;
        uint32_t nxt = rb ? gxs0 : gxs1;

        // refresh partner's h half (own half already live in hfull)
        const float* hrd = sH + rb * (25 * 128);
        if (lo) {
#pragma unroll
            for (int u = 14; u < 25; u++) hfull[u] = hrd[u * 128 + sidx];
        } else {
#pragma unroll
            for (int u = 0; u < 14; u++) hfull[u] = hrd[u * 128 + sidx];
        }

        // prefetch gx[t+1]
        if (t + 1 < TLEN) {
            const char* g = gxg + (((size_t)(t + 1) * NCHUNK + cbase) * NSEQ + n) * 16;
            uint32_t d = nxt + (cbase * 128 + sidx) * 16;
            for (int j = 0; j < cnum; j++) cpa16(d + j * 2048, g + (size_t)j * NSEQ * 16);
        }
        cpa_commit();

        // recurrent accumulators for this half's slots
        ull acc[22];
        if (lo) {
#pragma unroll
            for (int j = 0; j < 22; j++) acc[j] = (j >= 14 && j < 21) ? bIn[j - 14] : 0ull;
#pragma unroll
            for (int k = 0; k < HDIM; k++) {
                ull hd = fdup(hfull[k]);
                const ulonglong2* row = reinterpret_cast<const ulonglong2*>(&sW[k * SLOTS]);
#pragma unroll
                for (int j = 0; j < 11; j++) {
                    ulonglong2 w = row[j];
                    acc[2 * j]     = ffma2(w.x, hd, acc[2 * j]);
                    acc[2 * j + 1] = ffma2(w.y, hd, acc[2 * j + 1]);
                }
            }
        } else {
#pragma unroll
            for (int j = 0; j < 20; j++) acc[j] = (j >= 12 && j < 18) ? bIn[j - 12] : 0ull;
#pragma unroll
            for (int k = 0; k < HDIM; k++) {
                ull hd = fdup(hfull[k]);
                const ulonglong2* row =
                    reinterpret_cast<const ulonglong2*>(&sW[k * SLOTS + 24]);
#pragma unroll
                for (int j = 0; j < 10; j++) {
                    ulonglong2 w = row[j];
                    acc[2 * j]     = ffma2(w.x, hd, acc[2 * j]);
                    acc[2 * j + 1] = ffma2(w.y, hd, acc[2 * j + 1]);
                }
            }
        }

        // gx[t] resident (wait_group 1: only the t+1 group may remain in flight)
        cpa_wait1();
        union { uint4 v4[6]; __half2 h2[24]; } gx;
        {
            uint32_t a = cur + (cbase * 128 + sidx) * 16;
#pragma unroll
            for (int j = 0; j < 6; j++) {
                if (j < cnum)
                    asm volatile("ld.shared.v4.u32 {%0,%1,%2,%3}, [%4];"
                                 : "=r"(gx.v4[j].x), "=r"(gx.v4[j].y),
                                   "=r"(gx.v4[j].z), "=r"(gx.v4[j].w)
                                 : "r"(a + j * 2048));
            }
        }

        // gates: sig(v) = 0.5 + 0.5*tanh(v/2), /2 pre-folded into weights
        float* hwr = sH + wb * (25 * 128);
        if (lo) {
#pragma unroll
            for (int q = 0; q < 7; q++) {
                float2 gr = __half22float2(gx.h2[q]);
                float2 gz = __half22float2(gx.h2[7 + q]);
                float2 gn = __half22float2(gx.h2[14 + q]);
                float arl, arh; f2unpack(acc[q], arl, arh);
                float azl, azh; f2unpack(acc[7 + q], azl, azh);
                float anl, anh; f2unpack(acc[14 + q], anl, anh);
                float rl = fmaf(0.5f, tanhx(gr.x + arl), 0.5f);
                float rh = fmaf(0.5f, tanhx(gr.y + arh), 0.5f);
                float zl = fmaf(0.5f, tanhx(gz.x + azl), 0.5f);
                float zh = fmaf(0.5f, tanhx(gz.y + azh), 0.5f);
                float nl = tanhx(fmaf(rl, anl, gn.x));
                float nh = tanhx(fmaf(rh, anh, gn.y));
                hfull[2 * q]     = fmaf(zl, hfull[2 * q] - nl, nl);
                hfull[2 * q + 1] = fmaf(zh, hfull[2 * q + 1] - nh, nh);
            }
#pragma unroll
            for (int u = 0; u < 14; u++) hwr[u * 128 + sidx] = hfull[u];
        } else {
#pragma unroll
            for (int q = 0; q < 6; q++) {
                float2 gr = __half22float2(gx.h2[q]);
                float2 gz = __half22float2(gx.h2[6 + q]);
                float2 gn = __half22float2(gx.h2[12 + q]);
                float arl, arh; f2unpack(acc[q], arl, arh);
                float azl, azh; f2unpack(acc[6 + q], azl, azh);
                float anl, anh; f2unpack(acc[12 + q], anl, anh);
                float rl = fmaf(0.5f, tanhx(gr.x + arl), 0.5f);
                float zl = fmaf(0.5f, tanhx(gz.x + azl), 0.5f);
                float nl = tanhx(fmaf(rl, anl, gn.x));
                int u0 = 14 + 2 * q;
                hfull[u0] = fmaf(zl, hfull[u0] - nl, nl);
                if (u0 + 1 < 25) {  // unit 25 is padding
                    float rh = fmaf(0.5f, tanhx(gr.y + arh), 0.5f);
                    float zh = fmaf(0.5f, tanhx(gz.y + azh), 0.5f);
                    float nh = tanhx(fmaf(rh, anh, gn.y));
                    hfull[u0 + 1] = fmaf(zh, hfull[u0 + 1] - nh, nh);
                }
            }
#pragma unroll
            for (int u = 14; u < 25; u++) hwr[u * 128 + sidx] = hfull[u];
        }
        __syncthreads();
    }

    if (lo) {
#pragma unroll
        for (int u = 0; u < 14; u++) out[(size_t)n * HDIM + u] = hfull[u];
    } else {
#pragma unroll
        for (int u = 14; u < 25; u++) out[(size_t)n * HDIM + u] = hfull[u];
    }
}

// ---------------- launcher ----------------
extern "C" void kernel_launch(void* const* d_in, const int* in_sizes, int n_in,
                              void* d_out, int out_size) {
    (void)in_sizes; (void)n_in; (void)out_size;
    const float* x   = (const float*)d_in[0];
    const float* W1  = (const float*)d_in[1];
    const float* b1  = (const float*)d_in[2];
    const float* Wih = (const float*)d_in[3];
    const float* Whh = (const float*)d_in[4];
    const float* bih = (const float*)d_in[5];
    const float* bhh = (const float*)d_in[6];

    static bool attr_done = false;
    if (!attr_done) {
        cudaFuncSetAttribute(gru_kernel, cudaFuncAttributeMaxDynamicSharedMemorySize,
                             SMEM_TOT);
        attr_done = true;
    }

    prep_kernel<<<1, 256>>>(W1, b1, Wih, Whh, bih, bhh);
    gx_kernel<<<dim3(NSEQ / 128, TLEN / 2), 128>>>(x);
    gru_kernel<<<NSEQ / 128, 256, SMEM_TOT>>>((float*)d_out);
}

// round 14
// speedup vs baseline: 2.3765x; 1.6718x over previous
#include <cuda_runtime.h>
#include <cuda_fp16.h>
#include <cstdint>

// Problem constants
#define NSEQ   16384     // B*Ns
#define TLEN   128
#define CDIM   25
#define PDIM   20
#define HDIM   25
// Gate-column layout (N=96 MMA columns): col = gate*32 + unit  (unit 25..31 pad)
//   gate 0 = r, 1 = z, 2 = n
#define NCOL   96
#define NSLOT  48        // 48 half2 slots per (t, seq); slot p = cols 2p, 2p+1
#define NCHUNK 12        // 12 x 16B chunks (chunk ch = cols 8ch..8ch+7)

typedef unsigned long long ull;

// ---------------- packed f32x2 / misc helpers -------------
__device__ __forceinline__ ull ffma2(ull a, ull b, ull c) {
    ull d;
    asm("fma.rn.f32x2 %0, %1, %2, %3;" : "=l"(d) : "l"(a), "l"(b), "l"(c));
    return d;
}
__device__ __forceinline__ ull fdup(float v) {
    ull r;
    asm("mov.b64 %0, {%1, %1};" : "=l"(r) : "f"(v));
    return r;
}
__device__ __forceinline__ void f2unpack(ull v, float& lo, float& hi) {
    asm("mov.b64 {%0, %1}, %2;" : "=f"(lo), "=f"(hi) : "l"(v));
}
__device__ __forceinline__ float tanhx(float x) {
    float r; asm("tanh.approx.f32 %0, %1;" : "=f"(r) : "f"(x)); return r;
}
__device__ __forceinline__ ull pkbits(float lo, float hi) {
    return (ull)__float_as_uint(lo) | ((ull)__float_as_uint(hi) << 32);
}
__device__ __forceinline__ void cpa16(uint32_t smem_addr, const void* gptr) {
    asm volatile("cp.async.cg.shared.global [%0], [%1], 16;"
                 :: "r"(smem_addr), "l"(gptr));
}
__device__ __forceinline__ void cpa_commit() {
    asm volatile("cp.async.commit_group;");
}
__device__ __forceinline__ void cpa_wait1() {
    asm volatile("cp.async.wait_group 1;");
}
__device__ __forceinline__ uint32_t s2u(const void* p) {
    uint32_t a;
    asm("{ .reg .u64 t; cvta.to.shared.u64 t, %1; cvt.u32.u64 %0, t; }"
        : "=r"(a) : "l"(p));
    return a;
}
// pack two f32 into f16x2 reg: low = lo, high = hi  (PTX cvt d, src_hi, src_lo)
__device__ __forceinline__ uint32_t packh2(float lo, float hi) {
    uint32_t d;
    asm("cvt.rn.f16x2.f32 %0, %1, %2;" : "=r"(d) : "f"(hi), "f"(lo));
    return d;
}
// m16n8k16 f16 MMA with fp32 accum (sm_80+ baseline; legal on plain sm_103)
__device__ __forceinline__ void mma16816(float* d, const uint32_t* a,
                                         const uint32_t* b, const float* c) {
    asm volatile(
        "mma.sync.aligned.m16n8k16.row.col.f32.f16.f16.f32 "
        "{%0,%1,%2,%3}, {%4,%5,%6,%7}, {%8,%9}, {%10,%11,%12,%13};"
        : "=f"(d[0]), "=f"(d[1]), "=f"(d[2]), "=f"(d[3])
        : "r"(a[0]), "r"(a[1]), "r"(a[2]), "r"(a[3]),
          "r"(b[0]), "r"(b[1]),
          "f"(c[0]), "f"(c[1]), "f"(c[2]), "f"(c[3]));
}

// slot p -> (gate, first unit)
__device__ __forceinline__ void slot_decode(int p, int& g, int& u0) {
    g = p / 16; u0 = 2 * (p % 16);
}

// ---------------- device scratch (static: no allocation) ----------------
__device__ ull    g_pW1[CDIM * 10];        // [k][jp] W1 column pairs
__device__ ull    g_pb1[10];
__device__ ull    g_pWih[PDIM * NSLOT];    // [k][slot]; r,z pre-scaled 0.5
__device__ ull    g_bias_gx[NSLOT];        // r,z: 0.5*(b_ih+b_hh); n: b_ih
__device__ __half g_Bhh16[NCOL * 32];      // W_hh fp16 table [col][k] (K padded to 32)
__device__ float  g_bhn[NCOL];             // b_hh(n) per column (0 off n-gate / pads)
__device__ uint4  g_gx[(size_t)TLEN * NCHUNK * NSEQ];   // 402 MB, [t][chunk][n]

// ---------------- prep ----------------
__global__ void prep_kernel(const float* __restrict__ W1, const float* __restrict__ b1,
                            const float* __restrict__ Wih, const float* __restrict__ Whh,
                            const float* __restrict__ bih, const float* __restrict__ bhh) {
    int tid = threadIdx.x;
    for (int i = tid; i < CDIM * 10; i += blockDim.x) {
        int k = i / 10, jp = i % 10;
        g_pW1[i] = pkbits(W1[(2 * jp) * CDIM + k], W1[(2 * jp + 1) * CDIM + k]);
    }
    for (int i = tid; i < 10; i += blockDim.x)
        g_pb1[i] = pkbits(b1[2 * i], b1[2 * i + 1]);

    // W_ih pairs in gate-column layout (0.5 fold on r,z for tanh-sigmoid)
    for (int i = tid; i < PDIM * NSLOT; i += blockDim.x) {
        int k = i / NSLOT, p = i % NSLOT;
        int g, u0; slot_decode(p, g, u0);
        float sc = (g < 2) ? 0.5f : 1.0f;
        float lo = (u0 < 25)     ? sc * Wih[(g * 25 + u0) * PDIM + k] : 0.f;
        float hi = (u0 + 1 < 25) ? sc * Wih[(g * 25 + u0 + 1) * PDIM + k] : 0.f;
        g_pWih[i] = pkbits(lo, hi);
    }
    for (int i = tid; i < NSLOT; i += blockDim.x) {
        int g, u0; slot_decode(i, g, u0);
        float lo = 0.f, hi = 0.f;
        if (g < 2) {
            if (u0 < 25)     lo = 0.5f * (bih[g * 25 + u0] + bhh[g * 25 + u0]);
            if (u0 + 1 < 25) hi = 0.5f * (bih[g * 25 + u0 + 1] + bhh[g * 25 + u0 + 1]);
        } else {
            if (u0 < 25)     lo = bih[50 + u0];
            if (u0 + 1 < 25) hi = bih[50 + u0 + 1];
        }
        g_bias_gx[i] = pkbits(lo, hi);
    }
    // W_hh fp16 table [col c][k0..31], plain row-major
    for (int i = tid; i < NCOL * 32; i += blockDim.x) {
        int c = i / 32, k = i % 32;
        int g = c / 32, u = c % 32;
        float val = (u < 25 && k < 25)
                        ? ((g < 2) ? 0.5f : 1.0f) * Whh[(g * 25 + u) * HDIM + k]
                        : 0.f;
        g_Bhh16[i] = __float2half_rn(val);
    }
    for (int i = tid; i < NCOL; i += blockDim.x) {
        int g = i / 32, u = i % 32;
        g_bhn[i] = (g == 2 && u < 25) ? bhh[50 + u] : 0.f;
    }
}

// ---------------- K1: gx = leakyrelu(x@W1^T+b1)@Wih^T + bias -> fp16 chunks -------
__global__ __launch_bounds__(128, 1) void gx_kernel(const float* __restrict__ x) {
    __shared__ ull sW1[CDIM * 10];
    __shared__ ull sb1[10];
    __shared__ ull sWih[PDIM * NSLOT];
    __shared__ ull sbias[NSLOT];
    for (int i = threadIdx.x; i < CDIM * 10; i += 128) sW1[i] = g_pW1[i];
    for (int i = threadIdx.x; i < 10; i += 128) sb1[i] = g_pb1[i];
    for (int i = threadIdx.x; i < PDIM * NSLOT; i += 128) sWih[i] = g_pWih[i];
    for (int i = threadIdx.x; i < NSLOT; i += 128) sbias[i] = g_bias_gx[i];
    __syncthreads();

    int n = blockIdx.x * 128 + threadIdx.x;
    int t0 = blockIdx.y * 2;

    const float2* xp = reinterpret_cast<const float2*>(x + ((size_t)n * TLEN + t0) * CDIM);
    float xv[50];
#pragma unroll
    for (int i = 0; i < 25; i++) {
        float2 v = __ldg(xp + i);
        xv[2 * i] = v.x; xv[2 * i + 1] = v.y;
    }

    // projection for both time rows
    ull pa0[10], pa1[10];
#pragma unroll
    for (int j = 0; j < 10; j++) { pa0[j] = sb1[j]; pa1[j] = sb1[j]; }
#pragma unroll
    for (int k = 0; k < CDIM; k++) {
        ull d0 = fdup(xv[k]);
        ull d1 = fdup(xv[25 + k]);
        const ulonglong2* row = reinterpret_cast<const ulonglong2*>(&sW1[k * 10]);
#pragma unroll
        for (int j = 0; j < 5; j++) {
            ulonglong2 w = row[j];
            pa0[2 * j]     = ffma2(w.x, d0, pa0[2 * j]);
            pa0[2 * j + 1] = ffma2(w.y, d0, pa0[2 * j + 1]);
            pa1[2 * j]     = ffma2(w.x, d1, pa1[2 * j]);
            pa1[2 * j + 1] = ffma2(w.y, d1, pa1[2 * j + 1]);
        }
    }
    float pv0[20], pv1[20];
#pragma unroll
    for (int j = 0; j < 10; j++) {
        float a, b;
        f2unpack(pa0[j], a, b);
        pv0[2 * j] = fmaxf(a, 0.01f * a); pv0[2 * j + 1] = fmaxf(b, 0.01f * b);
        f2unpack(pa1[j], a, b);
        pv1[2 * j] = fmaxf(a, 0.01f * a); pv1[2 * j + 1] = fmaxf(b, 0.01f * b);
    }

    // 3 accumulation phases of 16 slots (bounds register pressure)
#pragma unroll
    for (int c = 0; c < 3; c++) {
        ull ga0[16], ga1[16];
#pragma unroll
        for (int q = 0; q < 16; q++) { ga0[q] = sbias[c * 16 + q]; ga1[q] = sbias[c * 16 + q]; }
#pragma unroll
        for (int k = 0; k < PDIM; k++) {
            ull d0 = fdup(pv0[k]);
            ull d1 = fdup(pv1[k]);
            const ulonglong2* row =
                reinterpret_cast<const ulonglong2*>(&sWih[k * NSLOT + c * 16]);
#pragma unroll
            for (int q = 0; q < 8; q++) {
                ulonglong2 w = row[q];
                ga0[2 * q]     = ffma2(w.x, d0, ga0[2 * q]);
                ga0[2 * q + 1] = ffma2(w.y, d0, ga0[2 * q + 1]);
                ga1[2 * q]     = ffma2(w.x, d1, ga1[2 * q]);
                ga1[2 * q + 1] = ffma2(w.y, d1, ga1[2 * q + 1]);
            }
        }
        union { __half2 h2[16]; uint4 v4[4]; } ob0, ob1;
#pragma unroll
        for (int q = 0; q < 16; q++) {
            float a, b;
            f2unpack(ga0[q], a, b); ob0.h2[q] = __floats2half2_rn(a, b);
            f2unpack(ga1[q], a, b); ob1.h2[q] = __floats2half2_rn(a, b);
        }
#pragma unroll
        for (int ci = 0; ci < 4; ci++) {
            int ch = c * 4 + ci;
            g_gx[((size_t)t0 * NCHUNK + ch) * NSEQ + n]       = ob0.v4[ci];
            g_gx[((size_t)(t0 + 1) * NCHUNK + ch) * NSEQ + n] = ob1.v4[ci];
        }
    }
}

// ---------------- K2: GRU scan with warp-level HMMA recurrence ----------------
// Each warp owns 16 sequences, W_hh lives in registers as mma.sync B-fragments,
// and the D->A fragment-layout identity (gate stride 32 == 0 mod 8) makes the
// h update thread-local: NO smem h exchange, NO __syncthreads in the loop.
__global__ __launch_bounds__(256, 1) void gru_kernel(float* __restrict__ out) {
    __shared__ __align__(16) char sGx[8][2][NCHUNK * 256];   // 48 KB: per warp 2x3KB

    const int tid = threadIdx.x;
    const int w = tid >> 5, lane = tid & 31;
    const int g = lane >> 2, tig = lane & 3;
    const int nwbase = blockIdx.x * 128 + w * 16;

    // --- load W_hh B-fragments (once) ---
    // frag (nf, kf): b0 = B[k=16kf+2tig +{0,1}][n=8nf+g], b1 = ... k+8
    uint32_t Bf[24][2];
    {
        const uint32_t* bt = reinterpret_cast<const uint32_t*>(g_Bhh16);  // half2 idx = n*16 + k/2
#pragma unroll
        for (int nf = 0; nf < 12; nf++) {
            int n = 8 * nf + g;
#pragma unroll
            for (int kf = 0; kf < 2; kf++) {
                Bf[nf * 2 + kf][0] = bt[n * 16 + 8 * kf + tig];
                Bf[nf * 2 + kf][1] = bt[n * 16 + 8 * kf + tig + 4];
            }
        }
    }
    // b_hh(n) for this thread's 8 unit columns (unit = 8*jj + 2*tig + e)
    float bhn[8];
#pragma unroll
    for (int jj = 0; jj < 4; jj++) {
        bhn[2 * jj]     = g_bhn[64 + 8 * jj + 2 * tig];
        bhn[2 * jj + 1] = g_bhn[64 + 8 * jj + 2 * tig + 1];
    }

    const uint32_t sbase = s2u(&sGx[w][0][0]);
    const char* gxg = reinterpret_cast<const char*>(g_gx);
    const int fch = 2 * 0 + (lane >> 4);   // base chunk parity for this lane
    const int fs = lane & 15;

    // prefetch t=0 into buf 0: lane fetches chunks {2j + lane/16}, seq lane%16
    {
#pragma unroll
        for (int j = 0; j < 6; j++) {
            int ch = 2 * j + (lane >> 4);
            cpa16(sbase + ch * 256 + fs * 16,
                  gxg + (((size_t)0 * NCHUNK + ch) * NSEQ + nwbase + fs) * 16);
        }
        cpa_commit();
    }

    float h[2][8];
#pragma unroll
    for (int r = 0; r < 2; r++)
#pragma unroll
        for (int j = 0; j < 8; j++) h[r][j] = 0.f;
    uint32_t a[2][4];
#pragma unroll
    for (int kf = 0; kf < 2; kf++)
#pragma unroll
        for (int i = 0; i < 4; i++) a[kf][i] = 0u;

    const float zero4[4] = {0.f, 0.f, 0.f, 0.f};

#pragma unroll 1
    for (int t = 0; t < TLEN; t++) {
        const int buf = t & 1;
        // prefetch gx[t+1]
        if (t + 1 < TLEN) {
#pragma unroll
            for (int j = 0; j < 6; j++) {
                int ch = 2 * j + (lane >> 4);
                cpa16(sbase + (buf ^ 1) * (NCHUNK * 256) + ch * 256 + fs * 16,
                      gxg + (((size_t)(t + 1) * NCHUNK + ch) * NSEQ + nwbase + fs) * 16);
            }
        }
        cpa_commit();
        cpa_wait1();          // own groups: everything older than t+1 done
        __syncwarp();         // partner lanes' cp.async for t complete + visible

        // gather gx: gxv[row][chunk], half2 (cols 8ch+2tig, +1)
        uint32_t gxv[2][12];
#pragma unroll
        for (int r = 0; r < 2; r++)
#pragma unroll
            for (int ch = 0; ch < 12; ch++)
                asm volatile("ld.shared.u32 %0, [%1];"
                             : "=r"(gxv[r][ch])
                             : "r"(sbase + buf * (NCHUNK * 256) + ch * 256 +
                                   (g + 8 * r) * 16 + tig * 4));

        // gh = h @ W_hh^T : 12 n-frags x 2 k-frags
        float D[12][4];
#pragma unroll
        for (int nf = 0; nf < 12; nf++) {
            mma16816(D[nf], a[0], Bf[nf * 2 + 0], zero4);
            mma16816(D[nf], a[1], Bf[nf * 2 + 1], D[nf]);
        }

        // gates + h update: nf-group nf holds units 8nf+2tig+{0,1}, rows g, g+8
#pragma unroll
        for (int nf = 0; nf < 4; nf++) {
#pragma unroll
            for (int r = 0; r < 2; r++) {
                float2 xr = __half22float2(*reinterpret_cast<__half2*>(&gxv[r][nf]));
                float2 xz = __half22float2(*reinterpret_cast<__half2*>(&gxv[r][nf + 4]));
                float2 xn = __half22float2(*reinterpret_cast<__half2*>(&gxv[r][nf + 8]));
#pragma unroll
                for (int e = 0; e < 2; e++) {
                    int di = 2 * r + e;
                    float hr = D[nf][di], hz = D[nf + 4][di], hn = D[nf + 8][di];
                    float vx_r = e ? xr.y : xr.x;
                    float vx_z = e ? xz.y : xz.x;
                    float vx_n = e ? xn.y : xn.x;
                    float rr = fmaf(0.5f, tanhx(vx_r + hr), 0.5f);
                    float zz = fmaf(0.5f, tanhx(vx_z + hz), 0.5f);
                    float nn = tanhx(fmaf(rr, hn + bhn[2 * nf + e], vx_n));
                    float& hv = h[r][2 * nf + e];
                    hv = fmaf(zz, hv - nn, nn);
                }
            }
        }

        // repack A fragments from updated h (layout-preserving)
#pragma unroll
        for (int kf = 0; kf < 2; kf++) {
            a[kf][0] = packh2(h[0][4 * kf + 0], h[0][4 * kf + 1]);
            a[kf][1] = packh2(h[1][4 * kf + 0], h[1][4 * kf + 1]);
            a[kf][2] = packh2(h[0][4 * kf + 2], h[0][4 * kf + 3]);
            a[kf][3] = packh2(h[1][4 * kf + 2], h[1][4 * kf + 3]);
        }
    }

    // write out valid units (unit = 8*jj + 2*tig + e < 25)
#pragma unroll
    for (int r = 0; r < 2; r++) {
        int n = nwbase + g + 8 * r;
#pragma unroll
        for (int jj = 0; jj < 4; jj++) {
#pragma unroll
            for (int e = 0; e < 2; e++) {
                int u = 8 * jj + 2 * tig + e;
                if (u < 25) out[(size_t)n * HDIM + u] = h[r][2 * jj + e];
            }
        }
    }
}

// ---------------- launcher ----------------
extern "C" void kernel_launch(void* const* d_in, const int* in_sizes, int n_in,
                              void* d_out, int out_size) {
    (void)in_sizes; (void)n_in; (void)out_size;
    const float* x   = (const float*)d_in[0];
    const float* W1  = (const float*)d_in[1];
    const float* b1  = (const float*)d_in[2];
    const float* Wih = (const float*)d_in[3];
    const float* Whh = (const float*)d_in[4];
    const float* bih = (const float*)d_in[5];
    const float* bhh = (const float*)d_in[6];

    prep_kernel<<<1, 256>>>(W1, b1, Wih, Whh, bih, bhh);
    gx_kernel<<<dim3(NSEQ / 128, TLEN / 2), 128>>>(x);
    gru_kernel<<<NSEQ / 128, 256>>>((float*)d_out);
}

// round 15
// speedup vs baseline: 4.5285x; 1.9055x over previous
#include <cuda_runtime.h>
#include <cuda_fp16.h>
#include <cstdint>

// Problem constants
#define NSEQ 16384   // B*Ns
#define TLEN 128
#define CDIM 25
#define PDIM 20
#define HDIM 25
#define NCOL 96      // gate-column layout: col = gate*32 + unit (gate 0=r,1=z,2=n)

typedef unsigned long long ull;

// ---------------- helpers ----------------
__device__ __forceinline__ float tanhx(float x) {
    float r; asm("tanh.approx.f32 %0, %1;" : "=f"(r) : "f"(x)); return r;
}
// pack two f32 -> f16x2 (low = lo, high = hi)
__device__ __forceinline__ uint32_t packh2(float lo, float hi) {
    uint32_t d;
    asm("cvt.rn.f16x2.f32 %0, %1, %2;" : "=r"(d) : "f"(hi), "f"(lo));
    return d;
}
__device__ __forceinline__ void cpa16(uint32_t smem_addr, const void* gptr) {
    asm volatile("cp.async.cg.shared.global [%0], [%1], 16;"
                 :: "r"(smem_addr), "l"(gptr));
}
__device__ __forceinline__ void cpa_commit() {
    asm volatile("cp.async.commit_group;");
}
__device__ __forceinline__ void cpa_wait0() {
    asm volatile("cp.async.wait_group 0;");
}
__device__ __forceinline__ uint32_t s2u(const void* p) {
    uint32_t a;
    asm("{ .reg .u64 t; cvta.to.shared.u64 t, %1; cvt.u32.u64 %0, t; }"
        : "=r"(a) : "l"(p));
    return a;
}
// m16n8k16 f16 MMA, fp32 accum, D accumulates in place (C == D)
__device__ __forceinline__ void mma_acc(float* d, uint32_t a0, uint32_t a1,
                                        uint32_t a2, uint32_t a3,
                                        uint32_t b0, uint32_t b1) {
    asm volatile(
        "mma.sync.aligned.m16n8k16.row.col.f32.f16.f16.f32 "
        "{%0,%1,%2,%3}, {%4,%5,%6,%7}, {%8,%9}, {%0,%1,%2,%3};"
        : "+f"(d[0]), "+f"(d[1]), "+f"(d[2]), "+f"(d[3])
        : "r"(a0), "r"(a1), "r"(a2), "r"(a3), "r"(b0), "r"(b1));
}

// ---------------- device scratch (static: no allocation) ----------------
__device__ __half g_xT[(size_t)TLEN * NSEQ * 32];  // 134 MB: [t][n][32], col25 = 1.0
__device__ __half g_W1h[24 * 32];   // [outcol n<24][k<32]; k<25 = W1, k==25 = b1
__device__ __half g_Wih[NCOL * 32]; // [gatecol][k]; k<20 = sc*Wih, k==20 = folded bias
__device__ __half g_Whh[NCOL * 32]; // [gatecol][k<25] = sc*Whh
__device__ float  g_bhn[NCOL];      // b_hh(n) per gate column (0 elsewhere)

// ---------------- prep: fp16 weight tables ----------------
// sigmoid computed as 0.5 + 0.5*tanh(arg/2); the /2 pre-folded into r,z rows.
__global__ void prep_kernel(const float* __restrict__ W1, const float* __restrict__ b1,
                            const float* __restrict__ Wih, const float* __restrict__ Whh,
                            const float* __restrict__ bih, const float* __restrict__ bhh) {
    int tid = threadIdx.x;
    for (int i = tid; i < 24 * 32; i += blockDim.x) {
        int n = i / 32, k = i % 32;
        float v = 0.f;
        if (n < 20) {
            if (k < 25) v = W1[n * 25 + k];
            else if (k == 25) v = b1[n];        // meets xT col25 == 1.0
        }
        g_W1h[i] = __float2half_rn(v);
    }
    for (int i = tid; i < NCOL * 32; i += blockDim.x) {
        int c = i / 32, k = i % 32;
        int gate = c / 32, u = c % 32;
        float sc = (gate < 2) ? 0.5f : 1.0f;
        float vi = 0.f, vh = 0.f;
        if (u < 25) {
            if (k < PDIM) vi = sc * Wih[(gate * 25 + u) * PDIM + k];
            else if (k == 20)                    // bias row, meets p col20 == 1.0
                vi = (gate < 2) ? 0.5f * (bih[gate * 25 + u] + bhh[gate * 25 + u])
                                : bih[50 + u];
            if (k < HDIM) vh = sc * Whh[(gate * 25 + u) * HDIM + k];
        }
        g_Wih[i] = __float2half_rn(vi);
        g_Whh[i] = __float2half_rn(vh);
    }
    for (int i = tid; i < NCOL; i += blockDim.x) {
        int gate = i / 32, u = i % 32;
        g_bhn[i] = (gate == 2 && u < 25) ? bhh[50 + u] : 0.f;
    }
}

// ---------------- K_T: transpose x -> fp16 [t][n][32] (col25 = 1.0) ----------------
__global__ __launch_bounds__(128, 1) void kt_kernel(const float* __restrict__ x) {
    __shared__ float4 sx4[800];   // 12.8 KB: one sequence's [128 t][25 c]
    int n = blockIdx.x;
    const float4* xg = reinterpret_cast<const float4*>(x + (size_t)n * (TLEN * CDIM));
    for (int i = threadIdx.x; i < 800; i += 128) sx4[i] = xg[i];
    __syncthreads();
    const float* sx = reinterpret_cast<const float*>(sx4);
    int t = threadIdx.x;
    uint4* dp = reinterpret_cast<uint4*>(g_xT + ((size_t)t * NSEQ + n) * 32);
    union { __half hh[8]; uint4 v; } o;
#pragma unroll
    for (int b = 0; b < 4; b++) {
#pragma unroll
        for (int e = 0; e < 8; e++) {
            int c = b * 8 + e;
            float v = (c < 25) ? sx[t * 25 + c] : (c == 25 ? 1.0f : 0.0f);
            o.hh[e] = __float2half_rn(v);
        }
        dp[b] = o.v;
    }
}

// ---------------- fused GRU scan: x -> p -> gx -> gh all in warp HMMA ----------------
// Warp owns 16 seqs. Per step: 6 MMA (p, + leakyrelu), then per gate-col-block
// gx and gh ACCUMULATE into one D for r,z (separate for n). D->A fragment
// identity keeps everything thread-local: no __syncthreads in the loop.
__global__ __launch_bounds__(128, 1) void gru_kernel(float* __restrict__ out) {
    __shared__ __align__(16) char sX[4 * 2 * 16 * 80];   // 10 KB: 4 warps x 2 bufs x 16x80B

    const int tid = threadIdx.x;
    const int w = tid >> 5, lane = tid & 31;
    const int g = lane >> 2, tig = lane & 3;
    const int n0 = blockIdx.x * 64 + w * 16;

    // B fragments (registers, loaded once; frag (nf,kf): k = 16kf+2tig+{0,1}, +8)
    uint32_t Bw1[3][2][2], Bih[12][2][2], Bhh[12][2][2];
    {
        const uint32_t* p1 = reinterpret_cast<const uint32_t*>(g_W1h);
        const uint32_t* pi = reinterpret_cast<const uint32_t*>(g_Wih);
        const uint32_t* ph = reinterpret_cast<const uint32_t*>(g_Whh);
#pragma unroll
        for (int nf = 0; nf < 12; nf++) {
            int n = 8 * nf + g;
#pragma unroll
            for (int kf = 0; kf < 2; kf++) {
                if (nf < 3) {
                    Bw1[nf][kf][0] = p1[n * 16 + 8 * kf + tig];
                    Bw1[nf][kf][1] = p1[n * 16 + 8 * kf + tig + 4];
                }
                Bih[nf][kf][0] = pi[n * 16 + 8 * kf + tig];
                Bih[nf][kf][1] = pi[n * 16 + 8 * kf + tig + 4];
                Bhh[nf][kf][0] = ph[n * 16 + 8 * kf + tig];
                Bhh[nf][kf][1] = ph[n * 16 + 8 * kf + tig + 4];
            }
        }
    }
    float bhn[8];
#pragma unroll
    for (int j = 0; j < 4; j++) {
        bhn[2 * j]     = g_bhn[64 + 8 * j + 2 * tig];
        bhn[2 * j + 1] = g_bhn[64 + 8 * j + 2 * tig + 1];
    }

    const uint32_t sb = s2u(sX) + w * 2560;   // per-warp 2 bufs x 16 rows x 80 B
    const char* xg = reinterpret_cast<const char*>(g_xT);

    auto prefetch = [&](int t, int buf) {
#pragma unroll
        for (int j = 0; j < 2; j++) {
            int idx = lane + 32 * j, row = idx >> 2, part = idx & 3;
            cpa16(sb + buf * 1280 + row * 80 + part * 16,
                  xg + ((size_t)t * NSEQ + n0 + row) * 64 + part * 16);
        }
        cpa_commit();
    };

    // p = leakyrelu(x @ W1ext^T) -> A fragments (p col20 forced to 1.0 for bias row)
    auto compute_ap = [&](int buf, uint32_t* ap) {
        uint32_t ax[2][4];
        uint32_t c0 = sb + buf * 1280;
#pragma unroll
        for (int kf = 0; kf < 2; kf++) {
            asm volatile("ld.shared.u32 %0, [%1];" : "=r"(ax[kf][0])
                         : "r"(c0 + g * 80 + (16 * kf + 2 * tig) * 2));
            asm volatile("ld.shared.u32 %0, [%1];" : "=r"(ax[kf][1])
                         : "r"(c0 + (g + 8) * 80 + (16 * kf + 2 * tig) * 2));
            asm volatile("ld.shared.u32 %0, [%1];" : "=r"(ax[kf][2])
                         : "r"(c0 + g * 80 + (16 * kf + 2 * tig + 8) * 2));
            asm volatile("ld.shared.u32 %0, [%1];" : "=r"(ax[kf][3])
                         : "r"(c0 + (g + 8) * 80 + (16 * kf + 2 * tig + 8) * 2));
        }
        float D0[4] = {0, 0, 0, 0}, D1[4] = {0, 0, 0, 0}, D2[4] = {0, 0, 0, 0};
        mma_acc(D0, ax[0][0], ax[0][1], ax[0][2], ax[0][3], Bw1[0][0][0], Bw1[0][0][1]);
        mma_acc(D0, ax[1][0], ax[1][1], ax[1][2], ax[1][3], Bw1[0][1][0], Bw1[0][1][1]);
        mma_acc(D1, ax[0][0], ax[0][1], ax[0][2], ax[0][3], Bw1[1][0][0], Bw1[1][0][1]);
        mma_acc(D1, ax[1][0], ax[1][1], ax[1][2], ax[1][3], Bw1[1][1][0], Bw1[1][1][1]);
        mma_acc(D2, ax[0][0], ax[0][1], ax[0][2], ax[0][3], Bw1[2][0][0], Bw1[2][0][1]);
        mma_acc(D2, ax[1][0], ax[1][1], ax[1][2], ax[1][3], Bw1[2][1][0], Bw1[2][1][1]);
#pragma unroll
        for (int i = 0; i < 4; i++) {
            D0[i] = fmaxf(D0[i], 0.01f * D0[i]);
            D1[i] = fmaxf(D1[i], 0.01f * D1[i]);
            D2[i] = fmaxf(D2[i], 0.01f * D2[i]);
        }
        ap[0] = packh2(D0[0], D0[1]);
        ap[1] = packh2(D0[2], D0[3]);
        ap[2] = packh2(D1[0], D1[1]);
        ap[3] = packh2(D1[2], D1[3]);
        float c20a = (tig == 2) ? 1.0f : D2[0];   // p col 20 := 1.0 (bias lane)
        float c20b = (tig == 2) ? 1.0f : D2[2];
        ap[4] = packh2(c20a, D2[1]);
        ap[5] = packh2(c20b, D2[3]);
    };

    // prologue
    prefetch(0, 0);
    cpa_wait0();
    __syncwarp();
    uint32_t apb[2][6];
    compute_ap(0, apb[0]);
    prefetch(1, 1);

    float h[2][8];
#pragma unroll
    for (int r = 0; r < 2; r++)
#pragma unroll
        for (int j = 0; j < 8; j++) h[r][j] = 0.f;
    uint32_t ah[2][4] = {{0, 0, 0, 0}, {0, 0, 0, 0}};
    const uint32_t z0 = 0;

#pragma unroll 2
    for (int t = 0; t < TLEN; t++) {
        const int cur = t & 1;

        // pipeline: finish x(t+1), build ap(t+1), start x(t+2)
        if (t + 1 < TLEN) {
            cpa_wait0();
            __syncwarp();
            compute_ap((t + 1) & 1, apb[(t + 1) & 1]);
            if (t + 2 < TLEN) prefetch(t + 2, cur);
        }

        const uint32_t* ap = apb[cur];
        // r,z: gx and gh accumulate into a single D; n: kept separate
        float Drz[8][4], Dxn[4][4], Dhn[4][4];
#pragma unroll
        for (int nf = 0; nf < 8; nf++) {
            Drz[nf][0] = Drz[nf][1] = Drz[nf][2] = Drz[nf][3] = 0.f;
            mma_acc(Drz[nf], ap[0], ap[1], ap[2], ap[3], Bih[nf][0][0], Bih[nf][0][1]);
            mma_acc(Drz[nf], ap[4], ap[5], z0, z0,       Bih[nf][1][0], Bih[nf][1][1]);
            mma_acc(Drz[nf], ah[0][0], ah[0][1], ah[0][2], ah[0][3],
                    Bhh[nf][0][0], Bhh[nf][0][1]);
            mma_acc(Drz[nf], ah[1][0], ah[1][1], ah[1][2], ah[1][3],
                    Bhh[nf][1][0], Bhh[nf][1][1]);
        }
#pragma unroll
        for (int j = 0; j < 4; j++) {
            int nf = 8 + j;
            Dxn[j][0] = Dxn[j][1] = Dxn[j][2] = Dxn[j][3] = 0.f;
            Dhn[j][0] = Dhn[j][1] = Dhn[j][2] = Dhn[j][3] = 0.f;
            mma_acc(Dxn[j], ap[0], ap[1], ap[2], ap[3], Bih[nf][0][0], Bih[nf][0][1]);
            mma_acc(Dxn[j], ap[4], ap[5], z0, z0,       Bih[nf][1][0], Bih[nf][1][1]);
            mma_acc(Dhn[j], ah[0][0], ah[0][1], ah[0][2], ah[0][3],
                    Bhh[nf][0][0], Bhh[nf][0][1]);
            mma_acc(Dhn[j], ah[1][0], ah[1][1], ah[1][2], ah[1][3],
                    Bhh[nf][1][0], Bhh[nf][1][1]);
        }

        // gates + h update (unit = 8j + 2tig + e, rows g, g+8)
#pragma unroll
        for (int j = 0; j < 4; j++) {
#pragma unroll
            for (int r = 0; r < 2; r++) {
#pragma unroll
                for (int e = 0; e < 2; e++) {
                    int di = 2 * r + e;
                    float rr = fmaf(0.5f, tanhx(Drz[j][di]), 0.5f);
                    float zz = fmaf(0.5f, tanhx(Drz[j + 4][di]), 0.5f);
                    float nn = tanhx(fmaf(rr, Dhn[j][di] + bhn[2 * j + e], Dxn[j][di]));
                    float& hv = h[r][2 * j + e];
                    hv = fmaf(zz, hv - nn, nn);
                }
            }
        }

        // repack A_h fragments from updated h (layout-preserving identity)
#pragma unroll
        for (int kf = 0; kf < 2; kf++) {
            ah[kf][0] = packh2(h[0][4 * kf + 0], h[0][4 * kf + 1]);
            ah[kf][1] = packh2(h[1][4 * kf + 0], h[1][4 * kf + 1]);
            ah[kf][2] = packh2(h[0][4 * kf + 2], h[0][4 * kf + 3]);
            ah[kf][3] = packh2(h[1][4 * kf + 2], h[1][4 * kf + 3]);
        }
    }

    // write valid units
#pragma unroll
    for (int r = 0; r < 2; r++) {
        int n = n0 + g + 8 * r;
#pragma unroll
        for (int j = 0; j < 4; j++) {
#pragma unroll
            for (int e = 0; e < 2; e++) {
                int u = 8 * j + 2 * tig + e;
                if (u < 25) out[(size_t)n * HDIM + u] = h[r][2 * j + e];
            }
        }
    }
}

// ---------------- launcher ----------------
extern "C" void kernel_launch(void* const* d_in, const int* in_sizes, int n_in,
                              void* d_out, int out_size) {
    (void)in_sizes; (void)n_in; (void)out_size;
    const float* x   = (const float*)d_in[0];
    const float* W1  = (const float*)d_in[1];
    const float* b1  = (const float*)d_in[2];
    const float* Wih = (const float*)d_in[3];
    const float* Whh = (const float*)d_in[4];
    const float* bih = (const float*)d_in[5];
    const float* bhh = (const float*)d_in[6];

    prep_kernel<<<1, 256>>>(W1, b1, Wih, Whh, bih, bhh);
    kt_kernel<<<NSEQ, 128>>>(x);
    gru_kernel<<<NSEQ / 64, 128>>>((float*)d_out);
}